// round 15
// baseline (speedup 1.0000x reference)
#include <cuda_runtime.h>
#include <cstddef>

// HealEncoding: out[b, f*NLVL + l] = sum_{n<4} params[l, neigh_pix[l,n,b], f] * neigh_weight[l,n,b]
// params: (8,196608,8) f32; neigh_pix: (8,4,1M) i32; neigh_weight: (8,4,1M) f32; out: (1M,64) f32

#define NLVL  8
#define NPIX  196608
#define BATCH 1000000
#define BBLK  64          // two 32-element passes per block

// Block (32,8): warp == one level. Pair-cooperative gather (lanes 2j,2j+1 split
// the 32B feature row; h = lane&1 -> 16B half): 1 l1tex wavefront per random
// pixel. R8 (137.8us) audit: every wavefront class is at its hardware floor
// (gathers=random lines, idx/w & STG = bytes/128B, STS/LDS = 1 phase/instr);
// measured dur is within ~4% of the floor. This round: two full passes per
// block (BBLK=64) to halve block-launch/drain overhead - the only non-floor
// cost left. Inner per-warp code byte-identical to R8.
__global__ void __launch_bounds__(256, 8)
heal_encoding_kernel(const float* __restrict__ params,
                     const int*   __restrict__ neigh_pix,
                     const float* __restrict__ neigh_weight,
                     float*       __restrict__ out)
{
    __shared__ float s[64 * 33];   // staging; addr = c*33 + (c>>5) + j2, conflict-free

    const int lane = threadIdx.x;
    const int lvl  = threadIdx.y;          // warp == level
    const int j    = lane >> 1;            // pixel-slot within warp [0,16)
    const int h    = lane & 1;             // 16B half of the 32B feature row
    const int tid  = lvl * 32 + lane;

    const float4* __restrict__ p4 =
        reinterpret_cast<const float4*>(params) + lvl * (NPIX * 2);

#pragma unroll
    for (int t2 = 0; t2 < 2; t2++) {
        const int b0 = blockIdx.x * BBLK + t2 * 32;

        // Vectorized idx/weight loads: int2/float2 covering elements (2j, 2j+1).
        int2   pix2[4];
        float2 w2[4];
#pragma unroll
        for (int n = 0; n < 4; n++) {
            const int off = (lvl * 4 + n) * BATCH + b0;   // fits int32
            pix2[n] = __ldg(reinterpret_cast<const int2*>(neigh_pix + off) + j);
            w2[n]   = __ldg(reinterpret_cast<const float2*>(neigh_weight + off) + j);
        }

#pragma unroll
        for (int s2 = 0; s2 < 2; s2++) {
            float4 a = make_float4(0.f, 0.f, 0.f, 0.f);

            // Neighbors in two pairs: 2 outstanding gathers per thread; at
            // 64 warps/SM that is ~128 in flight - latency fully hidden.
#pragma unroll
            for (int np = 0; np < 2; np++) {
                const int pa = (s2 == 0) ? pix2[2*np+0].x : pix2[2*np+0].y;
                const int pb = (s2 == 0) ? pix2[2*np+1].x : pix2[2*np+1].y;
                const float4 g0 = __ldg(&p4[pa * 2 + h]);
                const float4 g1 = __ldg(&p4[pb * 2 + h]);
                const float wa = (s2 == 0) ? w2[2*np+0].x : w2[2*np+0].y;
                const float wb = (s2 == 0) ? w2[2*np+1].x : w2[2*np+1].y;
                a.x = fmaf(wa, g0.x, a.x);  a.x = fmaf(wb, g1.x, a.x);
                a.y = fmaf(wa, g0.y, a.y);  a.y = fmaf(wb, g1.y, a.y);
                a.z = fmaf(wa, g0.z, a.z);  a.z = fmaf(wb, g1.z, a.z);
                a.w = fmaf(wa, g0.w, a.w);  a.w = fmaf(wb, g1.w, a.w);
            }

            // Stage element j2 = 2j+s2; out column c = (4h+k)*8 + lvl.
            // addr = c*33 + (c>>5) + j2 -> bank = const + 2j + h = const + lane:
            // conflict-free.
            const int j2 = 2 * j + s2;
#pragma unroll
            for (int k = 0; k < 4; k++) {
                const int c = (h * 4 + k) * NLVL + lvl;
                const float v = (k == 0) ? a.x : (k == 1) ? a.y : (k == 2) ? a.z : a.w;
                s[c * 33 + (c >> 5) + j2] = v;
            }
        }

        __syncthreads();

        // Coalesced write-out: 32 b x 64 cols = 2048 floats, 8 iters.
        // Read bank = (c + bl + const) % 32 distinct across warp: conflict-free.
        float* __restrict__ outp = out + (size_t)b0 * 64;
#pragma unroll
        for (int i = 0; i < 8; i++) {
            const int e  = i * 256 + tid;
            const int bl = e >> 6;
            const int c  = e & 63;
            outp[e] = s[c * 33 + (c >> 5) + bl];
        }

        if (t2 == 0) __syncthreads();   // staging tile reused by pass 2
    }
}

extern "C" void kernel_launch(void* const* d_in, const int* in_sizes, int n_in,
                              void* d_out, int out_size)
{
    const float* params       = (const float*)d_in[0];
    const int*   neigh_pix    = (const int*)d_in[1];
    const float* neigh_weight = (const float*)d_in[2];
    float*       out          = (float*)d_out;

    dim3 block(32, 8);
    dim3 grid(BATCH / BBLK);   // 15,625
    heal_encoding_kernel<<<grid, block>>>(params, neigh_pix, neigh_weight, out);
}

// round 17
// speedup vs baseline: 1.2430x; 1.2430x over previous
#include <cuda_runtime.h>
#include <cstddef>

// HealEncoding: out[b, f*NLVL + l] = sum_{n<4} params[l, neigh_pix[l,n,b], f] * neigh_weight[l,n,b]
// params: (8,196608,8) f32; neigh_pix: (8,4,1M) i32; neigh_weight: (8,4,1M) f32; out: (1M,64) f32
//
// FINAL (R8 champion, 137.8us). Block (32,8): warp == one level. Pair-cooperative
// gather: lanes 2j,2j+1 split the 32B feature row of pixel j (h = lane&1 picks
// the 16B half) -> one l1tex wavefront per random pixel (the hard floor).
// Vectorized int2/float2 idx/weight loads (1 wf per warp-load), conflict-free
// swizzled staging (addr = c*33 + (c>>5) + j2), coalesced 128B write-out.
// Measured at ~1.0 wavefront/cycle on l1tex with every wavefront class at its
// per-class floor; structural alternatives (persistence, SMEM/table gather,
// shuffle gather, larger blocks, multi-pass) all regressed 8-45%.

#define NLVL  8
#define NPIX  196608
#define BATCH 1000000
#define BBLK  32          // batch elements per block (2 per thread)

__global__ void __launch_bounds__(256, 8)
heal_encoding_kernel(const float* __restrict__ params,
                     const int*   __restrict__ neigh_pix,
                     const float* __restrict__ neigh_weight,
                     float*       __restrict__ out)
{
    __shared__ float s[64 * 33];   // staging; max addr 63*33+1+31 = 2111

    const int lane = threadIdx.x;
    const int lvl  = threadIdx.y;          // warp == level
    const int j    = lane >> 1;            // pixel-slot within warp [0,16)
    const int h    = lane & 1;             // 16B half of the 32B feature row
    const int b0   = blockIdx.x * BBLK;    // even

    const float4* __restrict__ p4 =
        reinterpret_cast<const float4*>(params) + lvl * (NPIX * 2);

    // Vectorized idx/weight loads: int2/float2 covering elements (2j, 2j+1).
    // Warp spans 16*8B = 128B = 1 wavefront per load. All-int32 offsets.
    int2   pix2[4];
    float2 w2[4];
#pragma unroll
    for (int n = 0; n < 4; n++) {
        const int off = (lvl * 4 + n) * BATCH + b0;   // < 32M, fits int32
        pix2[n] = __ldg(reinterpret_cast<const int2*>(neigh_pix + off) + j);
        w2[n]   = __ldg(reinterpret_cast<const float2*>(neigh_weight + off) + j);
    }

#pragma unroll
    for (int s2 = 0; s2 < 2; s2++) {
        float4 a = make_float4(0.f, 0.f, 0.f, 0.f);

        // Neighbors in two pairs: 2 outstanding gathers per thread keeps regs
        // at 32 (8 blocks/SM); at 64 warps/SM latency stays hidden.
#pragma unroll
        for (int np = 0; np < 2; np++) {
            const int pa = (s2 == 0) ? pix2[2*np+0].x : pix2[2*np+0].y;
            const int pb = (s2 == 0) ? pix2[2*np+1].x : pix2[2*np+1].y;
            const float4 g0 = __ldg(&p4[pa * 2 + h]);
            const float4 g1 = __ldg(&p4[pb * 2 + h]);
            const float wa = (s2 == 0) ? w2[2*np+0].x : w2[2*np+0].y;
            const float wb = (s2 == 0) ? w2[2*np+1].x : w2[2*np+1].y;
            a.x = fmaf(wa, g0.x, a.x);  a.x = fmaf(wb, g1.x, a.x);
            a.y = fmaf(wa, g0.y, a.y);  a.y = fmaf(wb, g1.y, a.y);
            a.z = fmaf(wa, g0.z, a.z);  a.z = fmaf(wb, g1.z, a.z);
            a.w = fmaf(wa, g0.w, a.w);  a.w = fmaf(wb, g1.w, a.w);
        }

        // Stage element j2 = 2j+s2; out column c = (4h+k)*8 + lvl.
        // addr = c*33 + (c>>5) + j2 -> store bank = const + 2j + h = const + lane:
        // conflict-free.
        const int j2 = 2 * j + s2;
#pragma unroll
        for (int k = 0; k < 4; k++) {
            const int c = (h * 4 + k) * NLVL + lvl;
            const float v = (k == 0) ? a.x : (k == 1) ? a.y : (k == 2) ? a.z : a.w;
            s[c * 33 + (c >> 5) + j2] = v;
        }
    }

    __syncthreads();

    // Coalesced write-out: 32 b x 64 cols = 2048 floats, 8 iters.
    // Read bank = (c + bl + const) % 32 distinct across warp: conflict-free.
    const int tid = lvl * 32 + lane;
    float* __restrict__ outp = out + (size_t)b0 * 64;
#pragma unroll
    for (int i = 0; i < 8; i++) {
        const int e  = i * 256 + tid;
        const int bl = e >> 6;
        const int c  = e & 63;
        outp[e] = s[c * 33 + (c >> 5) + bl];
    }
}

extern "C" void kernel_launch(void* const* d_in, const int* in_sizes, int n_in,
                              void* d_out, int out_size)
{
    const float* params       = (const float*)d_in[0];
    const int*   neigh_pix    = (const int*)d_in[1];
    const float* neigh_weight = (const float*)d_in[2];
    float*       out          = (float*)d_out;

    dim3 block(32, 8);
    dim3 grid(BATCH / BBLK);   // 31,250
    heal_encoding_kernel<<<grid, block>>>(params, neigh_pix, neigh_weight, out);
}